// round 10
// baseline (speedup 1.0000x reference)
#include <cuda_runtime.h>
#include <cstdint>

namespace {
constexpr int T_  = 1024;
constexpr int S_  = 64;
constexpr int D_  = 256;
constexpr int TP_ = 8;
constexpr int C_  = 65;      // 2*H*N_K + 1
constexpr int RING = 8;      // ring slots
constexpr int CHUNK_F4 = 16 * 64;        // 16 rows x 64 float4 = 16KB
constexpr unsigned CHUNK_BYTES = 16384u;
}

__device__ __forceinline__ unsigned pack_sgnabs(int v) {
    unsigned a = (unsigned)(v < 0 ? -v : v);
    return a | (v < 0 ? 0x80000000u : 0u);
}

__device__ __forceinline__ unsigned s2u(const void* p) {
    return (unsigned)__cvta_generic_to_shared(p);
}

__device__ __forceinline__ void mbar_wait(unsigned mbar, unsigned phase) {
    asm volatile(
        "{\n\t"
        ".reg .pred P1;\n\t"
        "LAB_WAIT%=:\n\t"
        "mbarrier.try_wait.parity.acquire.cta.shared::cta.b64 P1, [%0], %1, 0x989680;\n\t"
        "@P1 bra.uni LAB_DONE%=;\n\t"
        "bra.uni LAB_WAIT%=;\n\t"
        "LAB_DONE%=:\n\t"
        "}"
        :: "r"(mbar), "r"(phase) : "memory");
}

__device__ __forceinline__ void issue_chunk(const float* nei_emb, int t, int c,
                                            float4* ringp, int slot,
                                            unsigned long long* mbarp) {
    const float4* src = (const float4*)(nei_emb + (size_t)t * (S_ * D_)) + c * 1024;
    unsigned mb  = s2u(&mbarp[slot]);
    unsigned dst = s2u(&ringp[slot * CHUNK_F4]);
    asm volatile("mbarrier.arrive.expect_tx.shared.b64 _, [%0], %1;"
                 :: "r"(mb), "r"(CHUNK_BYTES) : "memory");
    asm volatile("cp.async.bulk.shared::cluster.global.mbarrier::complete_tx::bytes "
                 "[%0], [%1], %2, [%3];"
                 :: "r"(dst), "l"(src), "r"(CHUNK_BYTES), "r"(mb) : "memory");
}

__global__ __launch_bounds__(512, 1) void crit_main(
    const int*   __restrict__ sta_loc,
    const int*   __restrict__ nei_loc,
    const int*   __restrict__ rand_numbers,
    const float* __restrict__ sta_emb,
    const float* __restrict__ nei_emb,
    const float* __restrict__ mask,
    const float* __restrict__ rand_vals,
    const float* __restrict__ t_rand,
    float*       __restrict__ out)
{
    extern __shared__ float4 ring[];               // RING * 16KB = 128KB
    __shared__ float    s_cs[S_][TP_];
    __shared__ unsigned s_neiT[TP_][68];           // (sign<<31)|abs, transposed, padded
    __shared__ float    s_PT[TP_][68];             // sqrt(|eu|*mask) * B[s][p]
    __shared__ float    s_swc[68];                 // sqrt(|eu|*mask)/128
    __shared__ unsigned s_cnc[C_][TP_];
    __shared__ float    s_loss[C_][TP_];
    __shared__ float    s_lb0[32][TP_], s_lb1[32][TP_];   // high-half F partials
    __shared__ float    s_t32p[16];
    __shared__ float    s_mask[S_];
    __shared__ float    s_rns;
    __shared__ float    s_rv[TP_], s_rl[TP_], s_red2[TP_];
    __shared__ unsigned long long s_mbar[RING];

    const int tid  = threadIdx.x;                  // 0..511
    const int lane = tid & 31;
    const int warp = tid >> 5;                     // 0..15
    const int p    = tid & 7;
    const int htid = tid & 255;
    const int half = tid >> 8;                     // 0 or 1
    const int bid  = blockIdx.x;
    const int stride = gridDim.x;

    int nt = 0;
    for (int t = bid; t < T_; t += stride) nt++;
    const int totalChunks = nt * 4;

    // ---------------- mbar init + prologue issue (tid 0) ----------------
    if (tid == 0) {
        #pragma unroll
        for (int i = 0; i < RING; i++) {
            unsigned m = s2u(&s_mbar[i]);
            asm volatile("mbarrier.init.shared.b64 [%0], 1;" :: "r"(m) : "memory");
        }
        asm volatile("fence.proxy.async.shared::cta;" ::: "memory");
        int np = totalChunks < RING ? totalChunks : RING;
        for (int g = 0; g < np; g++)
            issue_chunk(nei_emb, bid + (g >> 2) * stride, g & 3, ring, g, s_mbar);
    }

    // ---------------- inline int64 stride detection ----------------
    int dlo = sta_loc[2 * lane];
    int dhi = sta_loc[2 * lane + 1];
    unsigned bmll = __ballot_sync(0xffffffffu, dhi == (dlo >> 31));
    const int str = (bmll == 0xffffffffu) ? 2 : 1;

    // ---------------- tile loop ----------------
    #pragma unroll 1
    for (int ti = 0; ti < nt; ti++) {
        const int t = bid + ti * stride;

        // sta slice in registers: every warp uses the same lane->slice map
        const float4* sg4 = (const float4*)(sta_emb + (size_t)t * D_);
        float4 sa0 = sg4[lane];
        float4 sa1 = sg4[lane + 32];
        if (warp == 0) {
            float ns = sa0.x*sa0.x + sa0.y*sa0.y + sa0.z*sa0.z + sa0.w*sa0.w
                     + sa1.x*sa1.x + sa1.y*sa1.y + sa1.z*sa1.z + sa1.w*sa1.w;
            #pragma unroll
            for (int o = 16; o; o >>= 1) ns += __shfl_xor_sync(0xffffffffu, ns, o);
            if (lane == 0) s_rns = rsqrtf(ns);
        }

        // small loads
        int nb = nei_loc[((size_t)t * (S_*TP_) + tid) * str];
        int rn = rand_numbers[((size_t)t * 256 + htid) * str];
        int sl = sta_loc[((size_t)t * TP_ + p) * str];
        if (tid < S_) s_mask[tid] = mask[(size_t)t * S_ + tid];
        float tr = 0.f;
        if (tid < TP_) {
            s_rv[tid] = rand_vals[(size_t)t * TP_ + tid];
            tr        = t_rand[t];
        }

        // D: cos_sn + packed nei (one (s,p) pair per thread)
        {
            int aa = sl < 0 ? -sl : sl;
            int s  = tid >> 3;
            int sg = ((nb ^ sl) < 0);
            int na = nb < 0 ? -nb : nb;
            unsigned x = (unsigned)(na ^ aa) + 1u;
            int v  = __clz((int)x) - 16;
            int iv = sg ? -v : v;
            s_cs[s][p]   = (float)iv * 0.0625f;
            s_neiT[p][s] = (unsigned)na | (nb < 0 ? 0x80000000u : 0u);
        }

        // E: cnc; F constants per-thread (both halves compute the same values)
        unsigned ca0, ca1, sflip;
        {
            int k = htid >> 4, c = htid >> 3;      // c = 2k+j
            int r = sl ^ (1 << k) ^ (rn & ((1 << k) - 1));
            ca0 = pack_sgnabs(r);
            ca1 = pack_sgnabs(-r);
            sflip = (ca0 ^ ca1) & 0x80000000u;
            if (tid < 256) { s_cnc[c][p] = ca0; s_cnc[c + 33][p] = ca1; }
            if (tid < TP_) s_cnc[32][tid] = pack_sgnabs(sl);
        }
        __syncthreads();                          // tile tables + s_rns ready

        float acc0 = 0.f, acc1 = 0.f, t32 = 0.f;
        const int c0 = htid >> 3;
        const int4*   nt4 = (const int4*)&s_neiT[p][0];
        const float4* ptv = (const float4*)&s_PT[p][0];
        const float4* swp = (const float4*)s_swc;

        #pragma unroll 1
        for (int c = 0; c < 4; c++) {
            const int g = ti * 4 + c, slot = g & 7;
            mbar_wait(s2u(&s_mbar[slot]), (unsigned)((g >> 3) & 1));

            // dot + C' : warp w handles chunk-row w (global s = c*16 + w)
            {
                const float4* nr = &ring[slot * CHUNK_F4 + warp * 64];
                float4 b0 = nr[lane];
                float4 b1 = nr[lane + 32];
                float dot = 0.f, nn = 0.f;
                dot = fmaf(sa0.x, b0.x, dot); dot = fmaf(sa0.y, b0.y, dot);
                dot = fmaf(sa0.z, b0.z, dot); dot = fmaf(sa0.w, b0.w, dot);
                dot = fmaf(sa1.x, b1.x, dot); dot = fmaf(sa1.y, b1.y, dot);
                dot = fmaf(sa1.z, b1.z, dot); dot = fmaf(sa1.w, b1.w, dot);
                nn  = fmaf(b0.x, b0.x, nn);  nn  = fmaf(b0.y, b0.y, nn);
                nn  = fmaf(b0.z, b0.z, nn);  nn  = fmaf(b0.w, b0.w, nn);
                nn  = fmaf(b1.x, b1.x, nn);  nn  = fmaf(b1.y, b1.y, nn);
                nn  = fmaf(b1.z, b1.z, nn);  nn  = fmaf(b1.w, b1.w, nn);
                #pragma unroll
                for (int o = 1; o < 32; o <<= 1) {
                    dot += __shfl_xor_sync(0xffffffffu, dot, o);
                    nn  += __shfl_xor_sync(0xffffffffu, nn,  o);
                }
                if (lane == 0) {
                    int s = c * 16 + warp;
                    float eu  = dot * rsqrtf(nn) * s_rns;
                    float4 caf = *(const float4*)&s_cs[s][0];
                    float4 cbf = *(const float4*)&s_cs[s][4];
                    float sum = caf.x + caf.y + caf.z + caf.w
                              + cbf.x + cbf.y + cbf.z + cbf.w;
                    float w   = fabsf(eu) * s_mask[s];
                    float sqw = sqrtf(w);
                    s_swc[s]  = sqw * 0.0078125f;
                    float cm  = fmaf(sum, 0.125f, -eu);
                    float csv[8] = {caf.x, caf.y, caf.z, caf.w, cbf.x, cbf.y, cbf.z, cbf.w};
                    #pragma unroll
                    for (int pp = 0; pp < 8; pp++)
                        s_PT[pp][s] = sqw * fmaf(csv[pp], -0.125f, cm);
                    t32 = fmaf(w * cm, cm, t32);
                }
            }
            __syncthreads();                      // slot consumed + P/swc ready

            if (tid == 0 && g + RING < totalChunks) {
                int g2 = g + RING;
                issue_chunk(nei_emb, bid + (g2 >> 2) * stride, g2 & 3, ring, slot, s_mbar);
            }

            // F partial for this chunk's 8 rows of this half
            #pragma unroll
            for (int k2 = 0; k2 < 2; k2++) {
                int idx = c * 4 + half * 2 + k2;
                int4   nv = nt4[idx];
                float4 Pv = ptv[idx];
                float4 sw = swp[idx];
                #pragma unroll
                for (int i = 0; i < 4; i++) {
                    unsigned ne = (i == 0) ? (unsigned)nv.x : (i == 1) ? (unsigned)nv.y
                                : (i == 2) ? (unsigned)nv.z : (unsigned)nv.w;
                    float P   = (i == 0) ? Pv.x : (i == 1) ? Pv.y : (i == 2) ? Pv.z : Pv.w;
                    float swv = (i == 0) ? sw.x : (i == 1) ? sw.y : (i == 2) ? sw.z : sw.w;
                    unsigned xr = ca0 ^ ne;
                    unsigned x1 = (xr & 0x1FFFFu) + 1u;
                    float uf = (float)(__clz((int)x1) - 16);
                    float us0 = __int_as_float(__float_as_int(uf) ^ (xr & 0x80000000u));
                    float us1 = __int_as_float(__float_as_int(us0) ^ sflip);
                    float h0 = fmaf(us0, swv, P);
                    float h1 = fmaf(us1, swv, P);
                    acc0 = fmaf(h0, h0, acc0);
                    acc1 = fmaf(h1, h1, acc1);
                }
            }
        }

        // ---------------- tile wrap-up ----------------
        if (lane == 0) s_t32p[warp] = t32;
        if (half == 1) { s_lb0[c0][p] = acc0; s_lb1[c0][p] = acc1; }
        __syncthreads();
        if (half == 0) {
            s_loss[c0][p]      = acc0 + s_lb0[c0][p];
            s_loss[c0 + 33][p] = acc1 + s_lb1[c0][p];
        }
        __syncthreads();

        // G: argmin, selection, outputs (8 threads)
        if (tid < TP_) {
            float l32 = 0.f;
            #pragma unroll
            for (int j = 0; j < 16; j++) l32 += s_t32p[j];
            float m8 = 0.f;
            #pragma unroll
            for (int j = 0; j < 8; j++) m8 += s_mask[tid * 8 + j];
            s_red2[tid] = m8;

            float best = s_loss[0][tid]; int bc = 0;
            #pragma unroll
            for (int c = 1; c < C_; c++) {
                float v = (c == 32) ? l32 : s_loss[c][tid];
                if (v < best) { best = v; bc = c; }       // first-occurrence argmin
            }
            float rv = s_rv[tid]; int rank = 0;
            #pragma unroll
            for (int q = 0; q < 8; q++) {
                float o = s_rv[q];
                rank += (o < rv) || (o == rv && q < tid); // stable argsort rank
            }
            int selg = (tr < 0.8f);
            int ci = (rank < 4) ? (selg ? bc : 32) : 32;
            unsigned pk = s_cnc[ci][tid];
            int val = (pk & 0x80000000u) ? -(int)(pk & 0x7fffffffu) : (int)pk;
            out[(size_t)t * TP_ + tid] = (float)val;
            s_rl[tid] = (ci == 32) ? l32 : s_loss[ci][tid];
            __syncwarp(0x000000ffu);
            if (tid == 0) {
                float rl = 0.f, lth = 0.f;
                #pragma unroll
                for (int q = 0; q < 8; q++) { rl += s_rl[q]; lth += s_red2[q]; }
                out[(size_t)T_ * TP_ + t] = rl * 0.125f / (lth + 1e-12f);
            }
        }
        __syncthreads();                          // protect tables before next tile
    }
}

extern "C" void kernel_launch(void* const* d_in, const int* in_sizes, int n_in,
                              void* d_out, int out_size) {
    (void)in_sizes; (void)n_in; (void)out_size;
    const int*   sta_loc      = (const int*)  d_in[0];
    const int*   nei_loc      = (const int*)  d_in[1];
    const int*   rand_numbers = (const int*)  d_in[2];
    const float* sta_emb      = (const float*)d_in[3];
    const float* nei_emb      = (const float*)d_in[4];
    const float* mask         = (const float*)d_in[5];
    const float* rand_vals    = (const float*)d_in[6];
    const float* t_rand       = (const float*)d_in[7];
    float* out = (float*)d_out;

    int sms = 148;
    cudaDeviceGetAttribute(&sms, cudaDevAttrMultiProcessorCount, 0);
    if (sms < 1)    sms = 148;
    if (sms > 1024) sms = 1024;

    cudaFuncSetAttribute(crit_main, cudaFuncAttributeMaxDynamicSharedMemorySize,
                         RING * (int)CHUNK_BYTES);
    crit_main<<<sms, 512, RING * CHUNK_BYTES>>>(sta_loc, nei_loc, rand_numbers,
                                                sta_emb, nei_emb, mask,
                                                rand_vals, t_rand, out);
}

// round 11
// speedup vs baseline: 1.5013x; 1.5013x over previous
#include <cuda_runtime.h>

namespace {
constexpr int T_  = 1024;
constexpr int S_  = 64;
constexpr int D_  = 256;
constexpr int TP_ = 8;
constexpr int C_  = 65;   // 2*H*N_K + 1
}

__device__ __forceinline__ unsigned pack_sgnabs(int v) {
    unsigned a = (unsigned)(v < 0 ? -v : v);
    return a | (v < 0 ? 0x80000000u : 0u);
}

__global__ __launch_bounds__(256, 4) void crit_main(
    const int*   __restrict__ sta_loc,
    const int*   __restrict__ nei_loc,
    const int*   __restrict__ rand_numbers,
    const float* __restrict__ sta_emb,
    const float* __restrict__ nei_emb,
    const float* __restrict__ mask,
    const float* __restrict__ rand_vals,
    const float* __restrict__ t_rand,
    float*       __restrict__ out)
{
    __shared__ float4   s_buf[2048];       // 32KB: rows 32..63 of this tile (LDGSTS)
    __shared__ float    s_eu[S_];          // raw dot*rsqrt(nn); scaled by rns in C'
    __shared__ float    s_mask[S_];
    __shared__ float    s_cs[S_][TP_];
    __shared__ unsigned s_neiT[TP_][68];   // transposed, padded: (sign<<31)|abs
    __shared__ float    s_PT[TP_][68];     // sqrt(|eu|*mask) * B[s][p]
    __shared__ float    s_swc[68];         // sqrt(|eu|*mask)/128
    __shared__ unsigned s_cnc[C_][TP_];    // packed (sign<<31)|abs
    __shared__ float    s_loss[C_][TP_];   // unnormalized by lth (argmin-invariant)
    __shared__ float    s_red[8];
    __shared__ float    s_l32[2];
    __shared__ float    s_invlth;
    __shared__ float    s_rv[TP_];
    __shared__ float    s_rl[TP_];

    const int t    = blockIdx.x;
    const int tid  = threadIdx.x;
    const int lane = tid & 31;
    const int warp = tid >> 5;
    const int p    = tid & 7;

    // ---------------- issue 32KB LDGSTS for rows 32..63 IMMEDIATELY ----------------
    // (register-free, so the whole 32KB queues at block start)
    {
        const float4* src = (const float4*)(nei_emb + (size_t)t * (S_ * D_)) + 2048 + tid * 8;
        unsigned dst = (unsigned)__cvta_generic_to_shared(s_buf) + tid * 128u;
        #pragma unroll
        for (int k = 0; k < 8; k++)
            asm volatile("cp.async.cg.shared.global [%0], [%1], 16;"
                         :: "r"(dst + k * 16u), "l"(src + k));
        asm volatile("cp.async.commit_group;" ::: "memory");
    }

    // ---------------- inline int64 detection (per-warp, no barrier) ----------------
    int dlo = sta_loc[2 * lane];
    int dhi = sta_loc[2 * lane + 1];
    unsigned bmll = __ballot_sync(0xffffffffu, dhi == (dlo >> 31));
    const int str = (bmll == 0xffffffffu) ? 2 : 1;

    // ---------------- small loads ----------------
    float sv = sta_emb[(size_t)t * D_ + tid];
    if (tid < S_)  s_mask[tid] = mask[(size_t)t * S_ + tid];
    float tr = 0.f;
    if (tid < TP_) {
        s_rv[tid] = rand_vals[(size_t)t * TP_ + tid];
        tr        = t_rand[t];
    }
    int nb0 = nei_loc[((size_t)t * (S_*TP_) + tid) * str];
    int nb1 = nei_loc[((size_t)t * (S_*TP_) + 256 + tid) * str];
    int rn  = rand_numbers[((size_t)t * 256 + tid) * str];
    int sl  = sta_loc[((size_t)t * TP_ + p) * str];

    // ---------------- B pass 1: rows 0..31 from gmem (LDG) ----------------
    const int q = lane & 7;
    const float4* sg4 = (const float4*)(sta_emb + (size_t)t * D_);
    {
        int row = warp * 4 + (lane >> 3);          // 0..31
        const float4* nr = (const float4*)(nei_emb + ((size_t)t * S_ + row) * D_);
        float dot = 0.f, nn = 0.f;
        #pragma unroll
        for (int j = 0; j < 8; j++) {
            float4 bb = nr[q + 8 * j];
            float4 a  = sg4[q + 8 * j];
            dot = fmaf(a.x, bb.x, dot); dot = fmaf(a.y, bb.y, dot);
            dot = fmaf(a.z, bb.z, dot); dot = fmaf(a.w, bb.w, dot);
            nn  = fmaf(bb.x, bb.x, nn); nn  = fmaf(bb.y, bb.y, nn);
            nn  = fmaf(bb.z, bb.z, nn); nn  = fmaf(bb.w, bb.w, nn);
        }
        #pragma unroll
        for (int o = 1; o < 8; o <<= 1) {
            dot += __shfl_xor_sync(0xffffffffu, dot, o);
            nn  += __shfl_xor_sync(0xffffffffu, nn,  o);
        }
        if (q == 0) s_eu[row] = dot * rsqrtf(nn);
    }

    // ---------------- D: cos_sn + packed nei (overlaps in-flight LDGSTS) ----------------
    {
        int aa = sl < 0 ? -sl : sl;
        #pragma unroll
        for (int it = 0; it < 2; it++) {
            int idx = tid + it * 256;
            int nb  = it ? nb1 : nb0;
            int s = idx >> 3;
            int sg = ((nb ^ sl) < 0);
            int na = nb < 0 ? -nb : nb;
            unsigned x = (unsigned)(na ^ aa) + 1u;
            int v  = __clz((int)x) - 16;
            int iv = sg ? -v : v;
            s_cs[s][p]   = (float)iv * 0.0625f;
            s_neiT[p][s] = (unsigned)na | (nb < 0 ? 0x80000000u : 0u);
        }
    }

    // ---------------- E: cnc packed ----------------
    {
        int k = tid >> 4, c = tid >> 3;   // c = 2k+j
        int r = sl ^ (1 << k) ^ (rn & ((1 << k) - 1));
        s_cnc[c][p]      = pack_sgnabs(r);
        s_cnc[c + 33][p] = pack_sgnabs(-r);
        if (tid < TP_) s_cnc[32][tid] = pack_sgnabs(sl);
    }

    // |sta|^2 partial reduce
    float ns = sv * sv;
    #pragma unroll
    for (int o = 16; o; o >>= 1) ns += __shfl_xor_sync(0xffffffffu, ns, o);
    if (lane == 0) s_red[warp] = ns;

    // ---------------- wait LDGSTS, then B pass 2: rows 32..63 from smem ----------------
    asm volatile("cp.async.wait_group 0;" ::: "memory");
    __syncthreads();                      // barrier 1: s_buf + all prologue smem visible
    {
        int rowL = warp * 4 + (lane >> 3);         // 0..31 (global row 32+rowL)
        const float4* nr = s_buf + rowL * 64;
        float dot = 0.f, nn = 0.f;
        #pragma unroll
        for (int j = 0; j < 8; j++) {
            float4 bb = nr[q + 8 * j];
            float4 a  = sg4[q + 8 * j];             // L1 hit
            dot = fmaf(a.x, bb.x, dot); dot = fmaf(a.y, bb.y, dot);
            dot = fmaf(a.z, bb.z, dot); dot = fmaf(a.w, bb.w, dot);
            nn  = fmaf(bb.x, bb.x, nn); nn  = fmaf(bb.y, bb.y, nn);
            nn  = fmaf(bb.z, bb.z, nn); nn  = fmaf(bb.w, bb.w, nn);
        }
        #pragma unroll
        for (int o = 1; o < 8; o <<= 1) {
            dot += __shfl_xor_sync(0xffffffffu, dot, o);
            nn  += __shfl_xor_sync(0xffffffffu, nn,  o);
        }
        if (q == 0) s_eu[32 + rowL] = dot * rsqrtf(nn);
    }
    __syncthreads();                      // barrier 2: all s_eu ready

    // ---------------- invlth (warp 2, parallel with C') ----------------
    if (warp == 2) {
        float m = s_mask[lane] + s_mask[lane + 32];
        #pragma unroll
        for (int o = 16; o; o >>= 1) m += __shfl_xor_sync(0xffffffffu, m, o);
        if (lane == 0) s_invlth = 1.0f / (m + 1e-12f);
    }

    // ---------------- C' (warps 0-1): P = sqw*B, swc = sqw/128, loss32 ----------------
    if (tid < S_) {
        float tot = s_red[0] + s_red[1] + s_red[2] + s_red[3]
                  + s_red[4] + s_red[5] + s_red[6] + s_red[7];
        float rns = rsqrtf(tot);
        int s = tid;
        float4 ca = *(const float4*)&s_cs[s][0];
        float4 cb = *(const float4*)&s_cs[s][4];
        float sum = ca.x + ca.y + ca.z + ca.w + cb.x + cb.y + cb.z + cb.w;
        float eu  = s_eu[s] * rns;
        float w   = fabsf(eu) * s_mask[s];   // lth factored out (argmin-invariant)
        float sqw = sqrtf(w);
        s_swc[s]  = sqw * 0.0078125f;
        float cm  = fmaf(sum, 0.125f, -eu);  // sum/8 - eu
        float csv[8] = {ca.x, ca.y, ca.z, ca.w, cb.x, cb.y, cb.z, cb.w};
        #pragma unroll
        for (int pp = 0; pp < 8; pp++)
            s_PT[pp][s] = sqw * fmaf(csv[pp], -0.125f, cm);
        float t32 = w * cm * cm;
        #pragma unroll
        for (int o = 16; o; o >>= 1) t32 += __shfl_xor_sync(0xffffffffu, t32, o);
        if (lane == 0) s_l32[warp] = t32;
    }
    __syncthreads();                      // barrier 3

    // ---------------- F: loss[c][p] and loss[c+33][p] share the clz chain ----------------
    {
        int c0 = tid >> 3;                 // 0..31
        unsigned ca0   = s_cnc[c0][p];
        unsigned ca1   = s_cnc[c0 + 33][p];
        unsigned sflip = (ca0 ^ ca1) & 0x80000000u;  // 0 iff r==0
        float acc0 = 0.f, acc1 = 0.f;
        const int4*   nt  = (const int4*)&s_neiT[p][0];
        const float4* ptv = (const float4*)&s_PT[p][0];
        const float4* swp = (const float4*)s_swc;
        #pragma unroll
        for (int s4 = 0; s4 < 16; s4++) {
            int4   nv = nt[s4];
            float4 Pv = ptv[s4];
            float4 sw = swp[s4];
            #pragma unroll
            for (int i = 0; i < 4; i++) {
                unsigned ne = (i == 0) ? (unsigned)nv.x : (i == 1) ? (unsigned)nv.y
                            : (i == 2) ? (unsigned)nv.z : (unsigned)nv.w;
                float P   = (i == 0) ? Pv.x : (i == 1) ? Pv.y : (i == 2) ? Pv.z : Pv.w;
                float swv = (i == 0) ? sw.x : (i == 1) ? sw.y : (i == 2) ? sw.z : sw.w;
                unsigned xr = ca0 ^ ne;
                unsigned x1 = (xr & 0x1FFFFu) + 1u;
                float uf = (float)(__clz((int)x1) - 16);
                float us0 = __int_as_float(__float_as_int(uf) ^ (xr & 0x80000000u));
                float us1 = __int_as_float(__float_as_int(us0) ^ sflip);
                float h0 = fmaf(us0, swv, P);
                float h1 = fmaf(us1, swv, P);
                acc0 = fmaf(h0, h0, acc0);
                acc1 = fmaf(h1, h1, acc1);
            }
        }
        s_loss[c0][p]      = acc0;
        s_loss[c0 + 33][p] = acc1;
        if (tid < TP_) s_loss[32][tid] = s_l32[0] + s_l32[1];
    }
    __syncthreads();                      // barrier 4

    // ---------------- G: argmin, selection, outputs ----------------
    if (tid < TP_) {
        float best = s_loss[0][tid]; int bc = 0;
        #pragma unroll
        for (int c = 1; c < C_; c++) {
            float v = s_loss[c][tid];
            if (v < best) { best = v; bc = c; }       // first-occurrence argmin
        }
        float rv = s_rv[tid]; int rank = 0;
        #pragma unroll
        for (int qq = 0; qq < 8; qq++) {
            float o = s_rv[qq];
            rank += (o < rv) || (o == rv && qq < tid); // stable argsort rank
        }
        int selg = (tr < 0.8f);
        int ci = (rank < 4) ? (selg ? bc : 32) : 32;
        unsigned pk = s_cnc[ci][tid];
        int val = (pk & 0x80000000u) ? -(int)(pk & 0x7fffffffu) : (int)pk;
        out[(size_t)t * TP_ + tid] = (float)val;
        s_rl[tid] = s_loss[ci][tid];
        __syncwarp(0x000000ffu);
        if (tid == 0) {
            float rl = 0.f;
            #pragma unroll
            for (int qq = 0; qq < 8; qq++) rl += s_rl[qq];
            out[(size_t)T_ * TP_ + t] = rl * 0.125f * s_invlth;
        }
    }
}

extern "C" void kernel_launch(void* const* d_in, const int* in_sizes, int n_in,
                              void* d_out, int out_size) {
    (void)in_sizes; (void)n_in; (void)out_size;
    const int*   sta_loc      = (const int*)  d_in[0];
    const int*   nei_loc      = (const int*)  d_in[1];
    const int*   rand_numbers = (const int*)  d_in[2];
    const float* sta_emb      = (const float*)d_in[3];
    const float* nei_emb      = (const float*)d_in[4];
    const float* mask         = (const float*)d_in[5];
    const float* rand_vals    = (const float*)d_in[6];
    const float* t_rand       = (const float*)d_in[7];
    float* out = (float*)d_out;

    crit_main<<<T_, 256>>>(sta_loc, nei_loc, rand_numbers,
                           sta_emb, nei_emb, mask, rand_vals, t_rand, out);
}

// round 12
// speedup vs baseline: 1.9599x; 1.3055x over previous
#include <cuda_runtime.h>

namespace {
constexpr int T_  = 1024;
constexpr int S_  = 64;
constexpr int D_  = 256;
constexpr int TP_ = 8;
constexpr int C_  = 65;   // 2*H*N_K + 1
}

__device__ __forceinline__ unsigned pack_sgnabs(int v) {
    unsigned a = (unsigned)(v < 0 ? -v : v);
    return a | (v < 0 ? 0x80000000u : 0u);
}

__global__ __launch_bounds__(256, 4) void crit_main(
    const int*   __restrict__ sta_loc,
    const int*   __restrict__ nei_loc,
    const int*   __restrict__ rand_numbers,
    const float* __restrict__ sta_emb,
    const float* __restrict__ nei_emb,
    const float* __restrict__ mask,
    const float* __restrict__ rand_vals,
    const float* __restrict__ t_rand,
    float*       __restrict__ out)
{
    __shared__ __align__(16) unsigned s_neiT[TP_][68];  // (sign<<31)|abs, transposed
    __shared__ __align__(16) float    s_PQ[TP_][68];    // w*B/64
    __shared__ __align__(16) float    s_P2[TP_][68];    // w*B^2
    __shared__ __align__(16) float    s_sw2[68];        // w/16384
    __shared__ __align__(16) float    s_t32[64];        // w*cm^2 per row
    __shared__ unsigned s_cnc[C_][TP_];
    __shared__ float    s_loss[C_][TP_];                // expanded loss minus SP2[p]
    __shared__ float    s_mask[S_];
    __shared__ float    s_rv[TP_], s_rl[TP_], s_red2[TP_];

    const int t    = blockIdx.x;
    const int tid  = threadIdx.x;
    const int lane = tid & 31;
    const int warp = tid >> 5;
    const int q    = lane & 7;             // == p for this thread

    // ---------------- inline int64 detection (per-warp, no barrier) ----------------
    int dlo = sta_loc[2 * lane];
    int dhi = sta_loc[2 * lane + 1];
    unsigned bmll = __ballot_sync(0xffffffffu, dhi == (dlo >> 31));
    const int str = (bmll == 0xffffffffu) ? 2 : 1;

    // ---------------- small loads ----------------
    const int sl = sta_loc[((size_t)t * TP_ + q) * str];
    int nbr[2];
    #pragma unroll
    for (int it = 0; it < 2; it++) {
        int row = warp * 8 + it * 4 + (lane >> 3);
        nbr[it] = nei_loc[(((size_t)t * S_ + row) * TP_ + q) * str];
    }
    int rn = rand_numbers[((size_t)t * 256 + tid) * str];
    if (tid < S_) s_mask[tid] = mask[(size_t)t * S_ + tid];
    float tr = 0.f;
    if (tid < TP_) {
        s_rv[tid] = rand_vals[(size_t)t * TP_ + tid];
        tr        = t_rand[t];
    }

    // ---------------- |sta|^2 within each 8-lane group (covers full row once) ----------------
    const float4* sg4 = (const float4*)(sta_emb + (size_t)t * D_);
    float ns = 0.f;
    #pragma unroll
    for (int j = 0; j < 8; j++) {
        float4 a = sg4[q + 8 * j];
        ns = fmaf(a.x, a.x, ns); ns = fmaf(a.y, a.y, ns);
        ns = fmaf(a.z, a.z, ns); ns = fmaf(a.w, a.w, ns);
    }
    #pragma unroll
    for (int o = 1; o < 8; o <<= 1) ns += __shfl_xor_sync(0xffffffffu, ns, o);
    const float rns = rsqrtf(ns);

    // ---------------- B' fused: dot + cos_sn + C' coefficients ----------------
    #pragma unroll
    for (int it = 0; it < 2; it++) {
        int row = warp * 8 + it * 4 + (lane >> 3);
        const float4* nr = (const float4*)(nei_emb + ((size_t)t * S_ + row) * D_);
        float dot = 0.f, nn = 0.f;
        #pragma unroll
        for (int j = 0; j < 8; j++) {
            float4 bb = nr[q + 8 * j];
            float4 a  = sg4[q + 8 * j];
            dot = fmaf(a.x, bb.x, dot); dot = fmaf(a.y, bb.y, dot);
            dot = fmaf(a.z, bb.z, dot); dot = fmaf(a.w, bb.w, dot);
            nn  = fmaf(bb.x, bb.x, nn); nn  = fmaf(bb.y, bb.y, nn);
            nn  = fmaf(bb.z, bb.z, nn); nn  = fmaf(bb.w, bb.w, nn);
        }
        // cos_sn for (row, p=q)
        int nb = nbr[it];
        int sg = ((nb ^ sl) < 0);
        int na = nb < 0 ? -nb : nb;
        int aa = sl < 0 ? -sl : sl;
        unsigned x = (unsigned)(na ^ aa) + 1u;
        int v  = __clz((int)x) - 16;
        int iv = sg ? -v : v;
        float cs = (float)iv * 0.0625f;
        s_neiT[q][row] = (unsigned)na | (nb < 0 ? 0x80000000u : 0u);
        float cssum = cs;
        #pragma unroll
        for (int o = 1; o < 8; o <<= 1) {
            dot   += __shfl_xor_sync(0xffffffffu, dot,   o);
            nn    += __shfl_xor_sync(0xffffffffu, nn,    o);
            cssum += __shfl_xor_sync(0xffffffffu, cssum, o);
        }
        float w = 0.f, cm = 0.f;
        if (q == 0) {
            float eu = dot * rsqrtf(nn) * rns;
            float mr = mask[(size_t)t * S_ + row];     // L1/L2 hit
            w  = fabsf(eu) * mr;                       // lth factored out
            cm = fmaf(cssum, 0.125f, -eu);             // cssum/8 - eu
        }
        w  = __shfl_sync(0xffffffffu, w,  0, 8);
        cm = __shfl_sync(0xffffffffu, cm, 0, 8);
        float B  = fmaf(cs, -0.125f, cm);
        float wB = w * B;
        s_PQ[q][row] = wB * 0.015625f;                 // w*B/64
        s_P2[q][row] = wB * B;                         // w*B^2
        if (q == 0) {
            s_sw2[row] = w * 6.103515625e-05f;         // w/16384
            s_t32[row] = w * cm * cm;
        }
    }

    // ---------------- E: cnc packed; F constants in registers ----------------
    unsigned ca0, ca1, sflip;
    {
        int k = tid >> 4, c = tid >> 3;                // c = 2k+j
        int r = sl ^ (1 << k) ^ (rn & ((1 << k) - 1));
        ca0 = pack_sgnabs(r);
        ca1 = pack_sgnabs(-r);
        sflip = (ca0 ^ ca1) & 0x80000000u;             // 0 iff r==0
        s_cnc[c][q]      = ca0;
        s_cnc[c + 33][q] = ca1;
        if (tid < TP_) s_cnc[32][tid] = pack_sgnabs(sl);
    }
    __syncthreads();                                   // barrier 1

    // ---------------- F: expanded loss, both mirrors from one chain ----------------
    {
        const int c0 = tid >> 3;                       // 0..31
        float accA = 0.f, accB = 0.f;
        const int4*   nt4 = (const int4*)&s_neiT[q][0];
        const float4* pqv = (const float4*)&s_PQ[q][0];
        const float4* swp = (const float4*)s_sw2;
        #pragma unroll
        for (int s4 = 0; s4 < 16; s4++) {
            int4   nv = nt4[s4];
            float4 Pq = pqv[s4];
            float4 sw = swp[s4];
            #pragma unroll
            for (int i = 0; i < 4; i++) {
                unsigned ne = (i == 0) ? (unsigned)nv.x : (i == 1) ? (unsigned)nv.y
                            : (i == 2) ? (unsigned)nv.z : (unsigned)nv.w;
                float PQ  = (i == 0) ? Pq.x : (i == 1) ? Pq.y : (i == 2) ? Pq.z : Pq.w;
                float sw2 = (i == 0) ? sw.x : (i == 1) ? sw.y : (i == 2) ? sw.z : sw.w;
                unsigned xr = ca0 ^ ne;
                unsigned x1 = (xr & 0x1FFFFu) + 1u;
                float uf = (float)(__clz((int)x1) - 16);
                float us = __int_as_float(__float_as_int(uf) ^ (xr & 0x80000000u));
                accA = fmaf(uf * uf, sw2, accA);
                accB = fmaf(us, PQ, accB);
            }
        }
        float accBs = __int_as_float(__float_as_int(accB) ^ sflip);
        s_loss[c0][q]      = accA + accB;              // true loss - SP2[p]
        s_loss[c0 + 33][q] = accA + accBs;
    }
    __syncthreads();                                   // barrier 2

    // ---------------- G: argmin, selection, outputs ----------------
    if (tid < TP_) {
        // SP2[p] = sum_s w*B^2  (additive constant over c; excluded from argmin)
        float SP2 = 0.f;
        const float4* pp = (const float4*)&s_P2[tid][0];
        #pragma unroll
        for (int j = 0; j < 16; j++) {
            float4 v4 = pp[j];
            SP2 += v4.x + v4.y + v4.z + v4.w;
        }
        float t32s = 0.f;
        const float4* tt = (const float4*)s_t32;
        #pragma unroll
        for (int j = 0; j < 16; j++) {
            float4 v4 = tt[j];
            t32s += v4.x + v4.y + v4.z + v4.w;
        }
        float l32adj = t32s - SP2;

        float best = s_loss[0][tid]; int bc = 0;
        #pragma unroll
        for (int c = 1; c < C_; c++) {
            float v = (c == 32) ? l32adj : s_loss[c][tid];
            if (v < best) { best = v; bc = c; }        // first-occurrence argmin
        }
        float rv = s_rv[tid]; int rank = 0;
        #pragma unroll
        for (int qq = 0; qq < 8; qq++) {
            float o = s_rv[qq];
            rank += (o < rv) || (o == rv && qq < tid); // stable argsort rank
        }
        int selg = (tr < 0.8f);
        int ci = (rank < 4) ? (selg ? bc : 32) : 32;
        unsigned pk = s_cnc[ci][tid];
        int val = (pk & 0x80000000u) ? -(int)(pk & 0x7fffffffu) : (int)pk;
        out[(size_t)t * TP_ + tid] = (float)val;
        s_rl[tid] = (ci == 32) ? t32s : (s_loss[ci][tid] + SP2);
        float m8 = 0.f;
        #pragma unroll
        for (int j = 0; j < 8; j++) m8 += s_mask[tid * 8 + j];
        s_red2[tid] = m8;
        __syncwarp(0x000000ffu);
        if (tid == 0) {
            float rl = 0.f, lth = 0.f;
            #pragma unroll
            for (int qq = 0; qq < 8; qq++) { rl += s_rl[qq]; lth += s_red2[qq]; }
            out[(size_t)T_ * TP_ + t] = rl * 0.125f / (lth + 1e-12f);
        }
    }
}

extern "C" void kernel_launch(void* const* d_in, const int* in_sizes, int n_in,
                              void* d_out, int out_size) {
    (void)in_sizes; (void)n_in; (void)out_size;
    const int*   sta_loc      = (const int*)  d_in[0];
    const int*   nei_loc      = (const int*)  d_in[1];
    const int*   rand_numbers = (const int*)  d_in[2];
    const float* sta_emb      = (const float*)d_in[3];
    const float* nei_emb      = (const float*)d_in[4];
    const float* mask         = (const float*)d_in[5];
    const float* rand_vals    = (const float*)d_in[6];
    const float* t_rand       = (const float*)d_in[7];
    float* out = (float*)d_out;

    crit_main<<<T_, 256>>>(sta_loc, nei_loc, rand_numbers,
                           sta_emb, nei_emb, mask, rand_vals, t_rand, out);
}